// round 1
// baseline (speedup 1.0000x reference)
#include <cuda_runtime.h>

// SparseBiasDiagUnfolder: gather off-diagonal 8x8 window entries.
// adj: (B=2, N=2048, N=2048, F=16) f32
// out: (B=2, S=511, 56*16=896) f32
// out[b, s, k*16+f] = adj[b, 4*s + ii(k), 4*s + jj(k), f]
// where local = k + 1 + k/8 (skips multiples of 9), ii = local/8, jj = local%8.

namespace {
constexpr int B  = 2;
constexpr int N  = 2048;
constexpr int S  = 511;   // number of window starts (0..2040 step 4)
constexpr int K  = 56;    // off-diagonal pairs per window
constexpr int TOT4 = B * S * K * 4;  // float4 elements of output = 228864
}

__global__ void __launch_bounds__(256)
sparse_diag_unfold_kernel(const float4* __restrict__ adj4,
                          float4* __restrict__ out4) {
    int t = blockIdx.x * blockDim.x + threadIdx.x;
    if (t >= TOT4) return;

    int f4   = t & 3;            // which float4 within the 16-float feature vec
    int t2   = t >> 2;           // (b, s, k)
    int k    = t2 % K;
    int rest = t2 / K;
    int s    = rest % S;
    int b    = rest / S;

    int local = k + 1 + (k >> 3);    // skip diagonal (multiples of 9)
    int r = (s << 2) + (local >> 3); // row = 4*s + ii
    int c = (s << 2) + (local & 7);  // col = 4*s + jj

    // adj element (b, r, c, f4*4..f4*4+3) as float4 index:
    // (((b*N + r)*N + c)*16 + f4*4) / 4 = ((b*N + r)*N + c)*4 + f4
    int src = (((b * N) + r) * N + c) * 4 + f4;
    out4[t] = __ldg(&adj4[src]);
}

extern "C" void kernel_launch(void* const* d_in, const int* in_sizes, int n_in,
                              void* d_out, int out_size) {
    const float4* adj4 = (const float4*)d_in[0];
    float4* out4 = (float4*)d_out;
    int blocks = (TOT4 + 255) / 256;
    sparse_diag_unfold_kernel<<<blocks, 256>>>(adj4, out4);
}